// round 9
// baseline (speedup 1.0000x reference)
#include <cuda_runtime.h>

// TemporalDecay: out = h + (1-M)*gamma*(h_fwd - h), gamma = exp(-relu(delta*W + b))
// h_fwd[b,t,j] = h[b, t-(delta-1), j], delta in {1..4} clamped to t+1, d = j % 64.
//
// R9 = R8 (transposed mapping, one thread per (row,d), __ldcs/__stcs policies)
// + gamma LUT in shared memory. gamma depends only on (delta in {2,3,4}, j):
// 768 entries, built once per block. Removes 8 W/b LDGs + the exp chain from
// the per-thread hot path (kernel is LSU-issue bound, ~45 LSU cyc/warp).
// LDS is conflict-free: lanes are consecutive d -> distinct banks.

#define B_    32
#define T_    2048
#define D_    64
#define KD_   256
#define TPB   256
#define NTHR  (B_ * T_ * D_)   // 4,194,304

__global__ __launch_bounds__(TPB, 8)
void temporal_decay_kernel(const float* __restrict__ h,
                           const float* __restrict__ dlt,
                           const float* __restrict__ m,
                           const float* __restrict__ W,
                           const float* __restrict__ Bv,
                           float* __restrict__ out)
{
    __shared__ float glut[3 * KD_];   // gamma[(delta-2)][j], delta = 2,3,4

    const int tid = threadIdx.x;

    // Build LUT: 768 entries, 3 per thread.
    #pragma unroll
    for (int e = tid; e < 3 * KD_; e += TPB) {
        const int   j  = e & (KD_ - 1);
        const float dd = (float)((e >> 8) + 2);
        glut[e] = fminf(__expf(-fmaf(dd, W[j], Bv[j])), 1.0f);
    }
    __syncthreads();

    const int i   = blockIdx.x * TPB + tid;
    const int d   = i & (D_ - 1);
    const int row = i >> 6;              // b*T + t

    // Uniform-per-thread small operands (read-once streams).
    const float df = __ldcs(dlt + i);
    const float mf = __ldcs(m + i);
    const int   di = (int)df;
    const float a  = 1.0f - mf;
    const bool  need = (mf == 0.0f) && (di > 1);

    const int base  = row * KD_ + d;                 // own element, k=0
    const int gbase = (row - di + 1) * KD_ + d;      // gather row base
    const int lbase = ((di - 2) << 8) + d;           // LUT row base (valid iff need)

    // Own values: each instr is one full 128B wavefront.
    const float h0 = h[base];
    const float h1 = h[base + 64];
    const float h2 = h[base + 128];
    const float h3 = h[base + 192];

    // Gathers + gamma, both predicated on `need` (delta==1 => out==h exactly).
    float c0 = 0.f, c1 = 0.f, c2 = 0.f, c3 = 0.f;
    float f0 = h0, f1 = h1, f2 = h2, f3 = h3;
    if (need) {
        f0 = __ldg(h + gbase);
        f1 = __ldg(h + gbase + 64);
        f2 = __ldg(h + gbase + 128);
        f3 = __ldg(h + gbase + 192);
        c0 = a * glut[lbase];
        c1 = a * glut[lbase + 64];
        c2 = a * glut[lbase + 128];
        c3 = a * glut[lbase + 192];
    }

    __stcs(out + base,       fmaf(c0, f0 - h0, h0));
    __stcs(out + base + 64,  fmaf(c1, f1 - h1, h1));
    __stcs(out + base + 128, fmaf(c2, f2 - h2, h2));
    __stcs(out + base + 192, fmaf(c3, f3 - h3, h3));
}

extern "C" void kernel_launch(void* const* d_in, const int* in_sizes, int n_in,
                              void* d_out, int out_size)
{
    const float* h_a    = (const float*)d_in[0];
    const float* deltas = (const float*)d_in[1];
    const float* M      = (const float*)d_in[2];
    const float* W      = (const float*)d_in[3];
    const float* bvec   = (const float*)d_in[4];
    float* out          = (float*)d_out;

    const int blocks = NTHR / TPB;   // 16384

    temporal_decay_kernel<<<blocks, TPB>>>(
        h_a, deltas, M, W, bvec, out);
}

// round 11
// speedup vs baseline: 1.2685x; 1.2685x over previous
#include <cuda_runtime.h>

// TemporalDecay: out = h + (1-M)*gamma*(h_fwd - h), gamma = exp(-relu(delta*W + b))
// h_fwd[b,t,j] = h[b, t-(delta-1), j], delta in {1..4} clamped to t+1, d = j % 64.
//
// R10: transposed mapping widened to a d-PAIR per thread (row, d2={d,d+1}),
// 8 outputs per thread via float2 accesses:
//  * per-output mem-instr count drops 5.5 -> 3.25 (40% LSU issue cut)
//  * delta/M/predicates uniform per d; all stream accesses full 128B wavefronts
//  * gathers remain stride-1 active-lane runs, predicated (delta==1 => out==h)
//  * register phasing: coefs computed and W/b retired before bulk h loads
//  * __ldcs/__stcs streaming policies kept from R8

#define B_    32
#define T_    2048
#define D_    64
#define KD_   256
#define TPB   256
#define NTHR  (B_ * T_ * D_ / 2)   // 2,097,152 threads (one d-pair each)

__global__ __launch_bounds__(TPB, 6)
void temporal_decay_kernel(const float*  __restrict__ h,
                           const float2* __restrict__ h2,
                           const float2* __restrict__ dlt2,
                           const float2* __restrict__ m2,
                           const float2* __restrict__ w2,
                           const float2* __restrict__ b2,
                           float2* __restrict__ out2)
{
    const int i   = blockIdx.x * TPB + threadIdx.x;
    const int p   = i & 31;              // d-pair index: d = 2p
    const int row = i >> 5;              // b*T + t

    // ---- phase 1: small operands -> coefs + gather state ----
    const float2 df = __ldcs(dlt2 + (row << 5) + p);
    const float2 mf = __ldcs(m2   + (row << 5) + p);

    const int dix = (int)df.x, diy = (int)df.y;
    const float ax = 1.0f - mf.x, ay = 1.0f - mf.y;
    const bool needx = (mf.x == 0.0f) && (dix > 1);
    const bool needy = (mf.y == 0.0f) && (diy > 1);

    const int base   = (row << 8) + (p << 1);          // scalar index, k=0, lane d
    const int gbasex = base - ((dix - 1) << 8);        // gather bases
    const int gbasey = base + 1 - ((diy - 1) << 8);

    // coef_k = (1-m) * min(exp(-(d*W+b)), 1)
    float cx[4], cy[4];
    #pragma unroll
    for (int k = 0; k < 4; ++k) {
        const float2 ww = w2[(k << 5) + p];
        const float2 bb = b2[(k << 5) + p];
        cx[k] = ax * fminf(__expf(-fmaf(df.x, ww.x, bb.x)), 1.0f);
        cy[k] = ay * fminf(__expf(-fmaf(df.y, ww.y, bb.y)), 1.0f);
    }

    // ---- phase 2: bulk loads (independent -> high MLP) ----
    float2 ha[4];
    #pragma unroll
    for (int k = 0; k < 4; ++k)
        ha[k] = h2[(base >> 1) + (k << 5)];

    float fx[4], fy[4];
    #pragma unroll
    for (int k = 0; k < 4; ++k) {
        fx[k] = needx ? __ldg(h + gbasex + (k << 6)) : ha[k].x;
        fy[k] = needy ? __ldg(h + gbasey + (k << 6)) : ha[k].y;
    }

    // ---- phase 3: blend + store ----
    #pragma unroll
    for (int k = 0; k < 4; ++k) {
        float2 o;
        o.x = fmaf(cx[k], fx[k] - ha[k].x, ha[k].x);
        o.y = fmaf(cy[k], fy[k] - ha[k].y, ha[k].y);
        __stcs(out2 + (base >> 1) + (k << 5), o);
    }
}

extern "C" void kernel_launch(void* const* d_in, const int* in_sizes, int n_in,
                              void* d_out, int out_size)
{
    const float* h_a    = (const float*)d_in[0];
    const float* deltas = (const float*)d_in[1];
    const float* M      = (const float*)d_in[2];
    const float* W      = (const float*)d_in[3];
    const float* bvec   = (const float*)d_in[4];
    float* out          = (float*)d_out;

    const int blocks = NTHR / TPB;   // 8192

    temporal_decay_kernel<<<blocks, TPB>>>(
        h_a, (const float2*)h_a,
        (const float2*)deltas, (const float2*)M,
        (const float2*)W, (const float2*)bvec,
        (float2*)out);
}